// round 7
// baseline (speedup 1.0000x reference)
#include <cuda_runtime.h>
#include <cuda_fp16.h>
#include <stdint.h>

// Problem constants (fixed by the dataset).
#define BATCH        64
#define N_FEAT       50000
#define UNITS        1024
#define CAP          2560   // per-column bucket capacity (mean 1953, sigma 44)
#define SPLIT        8      // segments per column in the main spmm
#define SCAT_ITEMS   4096   // nonzeros per scatter block
#define SCAT_THREADS 256
#define ITEMS_PT     (SCAT_ITEMS / SCAT_THREADS)   // 16

// ---------------------------------------------------------------------------
// Scratch (no allocations allowed -> __device__ globals)
// ---------------------------------------------------------------------------
__device__ __half   d_xTh[N_FEAT * BATCH];   // 6.4 MB: x transposed, fp16
__device__ unsigned d_packed[UNITS * CAP];   // 10.5 MB: (row<<16 | fp16 w) per column
__device__ int      d_counts[UNITS];         // global cursor == final count

// ---------------------------------------------------------------------------
// 0) zero d_counts (side stream, ahead of scatter)
// ---------------------------------------------------------------------------
__global__ void zero_counts_kernel() {
    d_counts[threadIdx.x] = 0;               // <<<1, 1024>>>
}

// ---------------------------------------------------------------------------
// 1) Transpose x[64][50000] -> d_xTh[50000][64] (fp16). 128 features/block,
//    float4 row loads (8 independent LDG.128/thread). Folds out zero-init.
// ---------------------------------------------------------------------------
__global__ __launch_bounds__(256) void transpose_kernel(
        const float* __restrict__ x, float* __restrict__ out) {
    __shared__ float4 tile4[32][65];         // [feat-chunk][batch], padded
    int tx = threadIdx.x & 31;               // float4-chunk within block tile
    int ty = threadIdx.x >> 5;               // 0..7
    int tid = threadIdx.x;
    int f0 = blockIdx.x * 128;               // first feature of this block
    int c0 = f0 >> 2;                        // first float4-chunk (N_FEAT/4=12500)

    // folded init: blocks 0..255 zero out (256*256 = 65536 = BATCH*UNITS)
    if (blockIdx.x < 256)
        out[blockIdx.x * 256 + tid] = 0.0f;

    const float4* __restrict__ x4 = reinterpret_cast<const float4*>(x);
    bool valid = (c0 + tx) < (N_FEAT / 4);
    if (valid) {
        #pragma unroll
        for (int r = ty; r < BATCH; r += 8)
            tile4[tx][r] = x4[(size_t)r * (N_FEAT / 4) + c0 + tx];
    }
    __syncthreads();

    // produce 128 features x 32 half2 = 4096 half2, coalesced writes
    const float* sf = reinterpret_cast<const float*>(tile4);
    __half2* xt2 = reinterpret_cast<__half2*>(d_xTh);
    #pragma unroll
    for (int i = 0; i < 16; i++) {
        int idx = tid + i * 256;             // 0..4095
        int fl  = idx >> 5;                  // local feature 0..127
        int b2  = idx & 31;                  // half2 index 0..31
        int f   = f0 + fl;
        if (f < N_FEAT) {
            int chunk = fl >> 2, comp = fl & 3;
            float va = sf[(chunk * 65 + 2 * b2) * 4 + comp];
            float vb = sf[(chunk * 65 + 2 * b2 + 1) * 4 + comp];
            xt2[(size_t)f * 32 + b2] = __floats2half2_rn(va, vb);
        }
    }
}

// ---------------------------------------------------------------------------
// 2) De-staged block-binned scatter: smem bin-count -> one global atomic per
//    (block, bin) -> DIRECT global write of packed (row<<16 | fp16 w).
// ---------------------------------------------------------------------------
__global__ __launch_bounds__(SCAT_THREADS) void scatter_kernel(
        const float* __restrict__ w,
        const int*   __restrict__ row_idx,
        const int*   __restrict__ col_idx, int nnz) {
    __shared__ int bcnt[UNITS];
    __shared__ int bbase[UNITS];

    int t = threadIdx.x;
    #pragma unroll
    for (int i = t; i < UNITS; i += SCAT_THREADS) bcnt[i] = 0;
    __syncthreads();

    int base = blockIdx.x * SCAT_ITEMS;

    // Phase 1: bin-count (smem atomics); remember (bin, local pos) packed.
    int pk[ITEMS_PT];
    #pragma unroll
    for (int k = 0; k < ITEMS_PT; k++) {
        int i = base + k * SCAT_THREADS + t;
        if (i < nnz) {
            int c = col_idx[i];
            int p = atomicAdd(&bcnt[c], 1);  // p < 4096, fits 13 bits
            pk[k] = (c << 13) | p;
        } else {
            pk[k] = -1;
        }
    }
    __syncthreads();

    // Phase 2: reserve global space, one atomic per non-empty (block, bin).
    #pragma unroll
    for (int i = t; i < UNITS; i += SCAT_THREADS) {
        int c = bcnt[i];
        if (c) bbase[i] = atomicAdd(&d_counts[i], c);
    }
    __syncthreads();

    // Phase 3: direct global write, 4B packed payload.
    #pragma unroll
    for (int k = 0; k < ITEMS_PT; k++) {
        if (pk[k] >= 0) {
            int i = base + k * SCAT_THREADS + t;
            int c = pk[k] >> 13;
            int p = pk[k] & 8191;
            int dst = bbase[c] + p;
            if (dst < CAP) {
                unsigned hw = (unsigned)__half_as_ushort(__float2half_rn(w[i]));
                d_packed[(size_t)c * CAP + dst] = ((unsigned)row_idx[i] << 16) | hw;
            }
        }
    }
}

// ---------------------------------------------------------------------------
// 3) Main SpMM, half-warp split: lanes 0-15 process nnz j, lanes 16-31 j+1.
//    Packed pair: one LDG.32 serves a half-warp (broadcast). Lane sub covers
//    batches [4*sub..4*sub+3] via one uint2 gather. 32-bit address math.
// ---------------------------------------------------------------------------
__global__ __launch_bounds__(256) void spmm_kernel(float* __restrict__ out) {
    int gwarp = (blockIdx.x * blockDim.x + threadIdx.x) >> 5;
    int lane  = threadIdx.x & 31;
    int col   = gwarp >> 3;
    int seg   = gwarp & (SPLIT - 1);
    if (col >= UNITS) return;

    int cnt = min(d_counts[col], CAP);
    int per = (cnt + SPLIT - 1) / SPLIT;
    int b0 = seg * per;
    int b1 = min(b0 + per, cnt);

    int h   = lane >> 4;        // half-warp id
    int sub = lane & 15;

    const unsigned* __restrict__ pairs = d_packed + (size_t)col * CAP;
    const uint2* __restrict__ xt = reinterpret_cast<const uint2*>(d_xTh);

    float2 a0 = make_float2(0.0f, 0.0f);   // batches 4*sub, 4*sub+1
    float2 a1 = make_float2(0.0f, 0.0f);   // batches 4*sub+2, 4*sub+3

    #pragma unroll 4
    for (int j = b0 + h; j < b1; j += 2) {
        unsigned p = __ldg(&pairs[j]);
        unsigned row = p >> 16;
        float wv = __half2float(__ushort_as_half((unsigned short)(p & 0xffffu)));
        uint2 v = __ldg(&xt[row * 16u + (unsigned)sub]);
        float2 f0 = __half22float2(*reinterpret_cast<__half2*>(&v.x));
        float2 f1 = __half22float2(*reinterpret_cast<__half2*>(&v.y));
        a0.x = fmaf(f0.x, wv, a0.x);
        a0.y = fmaf(f0.y, wv, a0.y);
        a1.x = fmaf(f1.x, wv, a1.x);
        a1.y = fmaf(f1.y, wv, a1.y);
    }

    a0.x += __shfl_xor_sync(0xffffffffu, a0.x, 16);
    a0.y += __shfl_xor_sync(0xffffffffu, a0.y, 16);
    a1.x += __shfl_xor_sync(0xffffffffu, a1.x, 16);
    a1.y += __shfl_xor_sync(0xffffffffu, a1.y, 16);

    if (h == 0) {
        int b = sub * 4;
        atomicAdd(&out[(b + 0) * UNITS + col], a0.x);
        atomicAdd(&out[(b + 1) * UNITS + col], a0.y);
        atomicAdd(&out[(b + 2) * UNITS + col], a1.x);
        atomicAdd(&out[(b + 3) * UNITS + col], a1.y);
    }
}

// ---------------------------------------------------------------------------
// Launch: fork/join so (zero_counts -> scatter) overlaps transpose.
// ---------------------------------------------------------------------------
extern "C" void kernel_launch(void* const* d_in, const int* in_sizes, int n_in,
                              void* d_out, int out_size) {
    const float* x       = (const float*)d_in[0];
    const float* w       = (const float*)d_in[1];
    const int*   row_idx = (const int*)d_in[2];
    const int*   col_idx = (const int*)d_in[3];
    float*       out     = (float*)d_out;
    int nnz = in_sizes[1];

    static cudaStream_t s2 = nullptr;
    static cudaEvent_t evFork = nullptr, evJoin = nullptr;
    if (s2 == nullptr) {
        cudaStreamCreateWithFlags(&s2, cudaStreamNonBlocking);
        cudaEventCreateWithFlags(&evFork, cudaEventDisableTiming);
        cudaEventCreateWithFlags(&evJoin, cudaEventDisableTiming);
    }

    // fork: side stream does counts-init + scatter
    cudaEventRecord(evFork, 0);
    cudaStreamWaitEvent(s2, evFork, 0);
    zero_counts_kernel<<<1, UNITS, 0, s2>>>();
    int sblocks = (nnz + SCAT_ITEMS - 1) / SCAT_ITEMS;
    scatter_kernel<<<sblocks, SCAT_THREADS, 0, s2>>>(w, row_idx, col_idx, nnz);
    cudaEventRecord(evJoin, s2);

    // main stream: transpose (+ out zero-init)
    transpose_kernel<<<(N_FEAT + 127) / 128, 256>>>(x, out);

    // join, then spmm
    cudaStreamWaitEvent(0, evJoin, 0);
    int total_warps = UNITS * SPLIT;
    int blocks = (total_warps * 32 + 255) / 256;
    spmm_kernel<<<blocks, 256>>>(out);
}

// round 8
// speedup vs baseline: 1.0835x; 1.0835x over previous
#include <cuda_runtime.h>
#include <cuda_fp16.h>
#include <stdint.h>

// Problem constants (fixed by the dataset).
#define BATCH        64
#define N_FEAT       50000
#define UNITS        1024
#define CAP          2560   // per-column bucket capacity (mean 1953, sigma 44)
#define SPLIT        8      // segments per column in the main spmm
#define SCAT_ITEMS   4096   // nonzeros per scatter block
#define SCAT_THREADS 256
#define ITEMS_PT     (SCAT_ITEMS / SCAT_THREADS)   // 16

// ---------------------------------------------------------------------------
// Scratch (no allocations allowed -> __device__ globals)
// ---------------------------------------------------------------------------
__device__ __half d_xTh[N_FEAT * BATCH];    // 6.4 MB: x transposed, fp16
__device__ int2   d_sorted[UNITS * CAP];    // 21 MB: per-column (row, w_bits)
__device__ int    d_counts[UNITS];          // global cursor == final count

// ---------------------------------------------------------------------------
// 0) zero d_counts (side stream, ahead of scatter)
// ---------------------------------------------------------------------------
__global__ void zero_counts_kernel() {
    d_counts[threadIdx.x] = 0;              // <<<1, 1024>>>
}

// ---------------------------------------------------------------------------
// 1) Transpose x[64][50000] -> d_xTh[50000][64] (fp16). 128 features/block,
//    float4 row loads. Folds out zero-init.
// ---------------------------------------------------------------------------
__global__ __launch_bounds__(256) void transpose_kernel(
        const float* __restrict__ x, float* __restrict__ out) {
    __shared__ float4 tile4[32][65];         // [feat-chunk][batch], padded
    int tx = threadIdx.x & 31;
    int ty = threadIdx.x >> 5;
    int tid = threadIdx.x;
    int f0 = blockIdx.x * 128;
    int c0 = f0 >> 2;

    if (blockIdx.x < 256)
        out[blockIdx.x * 256 + tid] = 0.0f;  // 256*256 = BATCH*UNITS

    const float4* __restrict__ x4 = reinterpret_cast<const float4*>(x);
    bool valid = (c0 + tx) < (N_FEAT / 4);
    if (valid) {
        #pragma unroll
        for (int r = ty; r < BATCH; r += 8)
            tile4[tx][r] = x4[(size_t)r * (N_FEAT / 4) + c0 + tx];
    }
    __syncthreads();

    const float* sf = reinterpret_cast<const float*>(tile4);
    __half2* xt2 = reinterpret_cast<__half2*>(d_xTh);
    #pragma unroll
    for (int i = 0; i < 16; i++) {
        int idx = tid + i * 256;             // 0..4095
        int fl  = idx >> 5;                  // local feature 0..127
        int b2  = idx & 31;                  // half2 index 0..31
        int f   = f0 + fl;
        if (f < N_FEAT) {
            int chunk = fl >> 2, comp = fl & 3;
            float va = sf[(chunk * 65 + 2 * b2) * 4 + comp];
            float vb = sf[(chunk * 65 + 2 * b2 + 1) * 4 + comp];
            xt2[(size_t)f * 32 + b2] = __floats2half2_rn(va, vb);
        }
    }
}

// ---------------------------------------------------------------------------
// 2) De-staged block-binned scatter: smem bin-count -> one global atomic per
//    (block, bin) -> DIRECT global write of int2 (row, fp32 w bits).
// ---------------------------------------------------------------------------
__global__ __launch_bounds__(SCAT_THREADS) void scatter_kernel(
        const float* __restrict__ w,
        const int*   __restrict__ row_idx,
        const int*   __restrict__ col_idx, int nnz) {
    __shared__ int bcnt[UNITS];
    __shared__ int bbase[UNITS];

    int t = threadIdx.x;
    #pragma unroll
    for (int i = t; i < UNITS; i += SCAT_THREADS) bcnt[i] = 0;
    __syncthreads();

    int base = blockIdx.x * SCAT_ITEMS;

    int pk[ITEMS_PT];
    #pragma unroll
    for (int k = 0; k < ITEMS_PT; k++) {
        int i = base + k * SCAT_THREADS + t;
        if (i < nnz) {
            int c = col_idx[i];
            int p = atomicAdd(&bcnt[c], 1);  // p < 4096, fits 13 bits
            pk[k] = (c << 13) | p;
        } else {
            pk[k] = -1;
        }
    }
    __syncthreads();

    #pragma unroll
    for (int i = t; i < UNITS; i += SCAT_THREADS) {
        int c = bcnt[i];
        if (c) bbase[i] = atomicAdd(&d_counts[i], c);
    }
    __syncthreads();

    #pragma unroll
    for (int k = 0; k < ITEMS_PT; k++) {
        if (pk[k] >= 0) {
            int i = base + k * SCAT_THREADS + t;
            int c = pk[k] >> 13;
            int p = pk[k] & 8191;
            int dst = bbase[c] + p;
            if (dst < CAP)
                d_sorted[(size_t)c * CAP + dst] =
                    make_int2(row_idx[i], __float_as_int(w[i]));
        }
    }
}

// ---------------------------------------------------------------------------
// 3) Main SpMM, quarter-warp split: quarter q (8 lanes) processes nnz j=b0+q,
//    step 4. Each lane gathers uint4 = 8 batches (one LDG.128, full 128B row
//    covered by 8 lanes). Pairs: int2, one 32B sector serves the whole warp's
//    4 in-flight nnz. ~4.25 warp-issues/nnz.
// ---------------------------------------------------------------------------
__global__ __launch_bounds__(256) void spmm_kernel(float* __restrict__ out) {
    int gwarp = (blockIdx.x * blockDim.x + threadIdx.x) >> 5;
    int lane  = threadIdx.x & 31;
    int col   = gwarp >> 3;
    int seg   = gwarp & (SPLIT - 1);
    if (col >= UNITS) return;

    int cnt = min(d_counts[col], CAP);
    int per = (cnt + SPLIT - 1) / SPLIT;
    int b0 = seg * per;
    int b1 = min(b0 + per, cnt);

    int q   = lane >> 3;        // quarter id 0..3
    int oct = lane & 7;         // lane within quarter

    const int2* __restrict__ pairs = d_sorted + (size_t)col * CAP;
    const uint4* __restrict__ xt4 = reinterpret_cast<const uint4*>(d_xTh);

    // batches 8*oct .. 8*oct+7
    float2 a0 = make_float2(0.f, 0.f), a1 = make_float2(0.f, 0.f);
    float2 a2 = make_float2(0.f, 0.f), a3 = make_float2(0.f, 0.f);

    #pragma unroll 2
    for (int j = b0 + q; j < b1; j += 4) {
        int2 p = __ldg(&pairs[j]);
        uint4 v = __ldg(&xt4[(unsigned)p.x * 8u + (unsigned)oct]);
        float wv = __int_as_float(p.y);
        float2 f0 = __half22float2(*reinterpret_cast<__half2*>(&v.x));
        float2 f1 = __half22float2(*reinterpret_cast<__half2*>(&v.y));
        float2 f2 = __half22float2(*reinterpret_cast<__half2*>(&v.z));
        float2 f3 = __half22float2(*reinterpret_cast<__half2*>(&v.w));
        a0.x = fmaf(f0.x, wv, a0.x);  a0.y = fmaf(f0.y, wv, a0.y);
        a1.x = fmaf(f1.x, wv, a1.x);  a1.y = fmaf(f1.y, wv, a1.y);
        a2.x = fmaf(f2.x, wv, a2.x);  a2.y = fmaf(f2.y, wv, a2.y);
        a3.x = fmaf(f3.x, wv, a3.x);  a3.y = fmaf(f3.y, wv, a3.y);
    }

    // reduce the 4 quarters (disjoint nnz, same batch mapping per oct)
    #pragma unroll
    for (int d = 8; d <= 16; d <<= 1) {
        a0.x += __shfl_xor_sync(0xffffffffu, a0.x, d);
        a0.y += __shfl_xor_sync(0xffffffffu, a0.y, d);
        a1.x += __shfl_xor_sync(0xffffffffu, a1.x, d);
        a1.y += __shfl_xor_sync(0xffffffffu, a1.y, d);
        a2.x += __shfl_xor_sync(0xffffffffu, a2.x, d);
        a2.y += __shfl_xor_sync(0xffffffffu, a2.y, d);
        a3.x += __shfl_xor_sync(0xffffffffu, a3.x, d);
        a3.y += __shfl_xor_sync(0xffffffffu, a3.y, d);
    }

    if (q == 0) {
        int b = oct * 8;
        atomicAdd(&out[(b + 0) * UNITS + col], a0.x);
        atomicAdd(&out[(b + 1) * UNITS + col], a0.y);
        atomicAdd(&out[(b + 2) * UNITS + col], a1.x);
        atomicAdd(&out[(b + 3) * UNITS + col], a1.y);
        atomicAdd(&out[(b + 4) * UNITS + col], a2.x);
        atomicAdd(&out[(b + 5) * UNITS + col], a2.y);
        atomicAdd(&out[(b + 6) * UNITS + col], a3.x);
        atomicAdd(&out[(b + 7) * UNITS + col], a3.y);
    }
}

// ---------------------------------------------------------------------------
// Launch: fork/join so (zero_counts -> scatter) overlaps transpose.
// ---------------------------------------------------------------------------
extern "C" void kernel_launch(void* const* d_in, const int* in_sizes, int n_in,
                              void* d_out, int out_size) {
    const float* x       = (const float*)d_in[0];
    const float* w       = (const float*)d_in[1];
    const int*   row_idx = (const int*)d_in[2];
    const int*   col_idx = (const int*)d_in[3];
    float*       out     = (float*)d_out;
    int nnz = in_sizes[1];

    static cudaStream_t s2 = nullptr;
    static cudaEvent_t evFork = nullptr, evJoin = nullptr;
    if (s2 == nullptr) {
        cudaStreamCreateWithFlags(&s2, cudaStreamNonBlocking);
        cudaEventCreateWithFlags(&evFork, cudaEventDisableTiming);
        cudaEventCreateWithFlags(&evJoin, cudaEventDisableTiming);
    }

    // fork: side stream does counts-init + scatter
    cudaEventRecord(evFork, 0);
    cudaStreamWaitEvent(s2, evFork, 0);
    zero_counts_kernel<<<1, UNITS, 0, s2>>>();
    int sblocks = (nnz + SCAT_ITEMS - 1) / SCAT_ITEMS;
    scatter_kernel<<<sblocks, SCAT_THREADS, 0, s2>>>(w, row_idx, col_idx, nnz);
    cudaEventRecord(evJoin, s2);

    // main stream: transpose (+ out zero-init)
    transpose_kernel<<<(N_FEAT + 127) / 128, 256>>>(x, out);

    // join, then spmm
    cudaStreamWaitEvent(0, evJoin, 0);
    int total_warps = UNITS * SPLIT;
    int blocks = (total_warps * 32 + 255) / 256;
    spmm_kernel<<<blocks, 256>>>(out);
}